// round 3
// baseline (speedup 1.0000x reference)
#include <cuda_runtime.h>

// Net_24395414241687 — GNN pipeline ending in log_softmax over a length-1
// axis => output is identically zeros([1024, 1]) for every input. The whole
// network is dead code; the only mandatory work is un-poisoning d_out.
//
// R1: grid=4 scalar-store kernel: 4.86us e2e.
// R2: cudaMemsetAsync node:       3.94us e2e (WIN — removed SM grid launch).
// R3: minimal 1-CTA kernel node — 1 block x 256 threads, one STG.128 of
//     zeros per thread (4KB total), no bounds check on the fast path
//     (out_size=1024 floats = 256 float4, exactly covered). Testing whether
//     a 1-CTA kernel node beats the memset node's front-end; if neutral or
//     worse, the single-node graph replay dispatch is the floor.

__global__ void __launch_bounds__(256, 1) net_zero_out_v4(float4* __restrict__ out, int n4) {
    int i = threadIdx.x;
    if (i < n4) out[i] = make_float4(0.f, 0.f, 0.f, 0.f);
}

extern "C" void kernel_launch(void* const* d_in, const int* in_sizes, int n_in,
                              void* d_out, int out_size) {
    (void)d_in; (void)in_sizes; (void)n_in;
    if ((out_size & 3) == 0 && out_size <= 1024) {
        // 1024 floats -> 256 float4 stores, exactly one 1-CTA launch.
        net_zero_out_v4<<<1, 256>>>((float4*)d_out, out_size >> 2);
    } else {
        // generic fallback (not taken for this problem's shape)
        cudaMemsetAsync(d_out, 0, (size_t)out_size * sizeof(float), 0);
    }
}

// round 4
// speedup vs baseline: 1.1520x; 1.1520x over previous
#include <cuda_runtime.h>

// Net_24395414241687 — two-layer NNConv GNN + readout ending in
// log_softmax over axis=1 of a [G, 1] = [1024, 1] tensor.
//
// log_softmax over a length-1 axis is identically zero:
//   log_softmax(x) = x - logsumexp(x) = x - x = 0  (bit-exact in JAX's
//   max-subtracted formulation; all upstream values finite).
// So the reference output is exactly zeros([1024, 1]) for every input and
// the entire GNN pipeline is dead code. The only mandatory work is
// un-poisoning d_out (harness fills it with 0xAA before timing).
//
// Measured ladder:
//   R1 grid=4 kernel node:   4.86us e2e (kernel node 3.39us)
//   R2 cudaMemsetAsync node: 3.94us e2e   <- WIN
//   R3 1-CTA kernel node:    4.61us e2e (kernel node 3.33us)
// Kernel-node front-end is ~3.3us regardless of grid/instruction count;
// the memset node type is ~1.4us cheaper. Remaining e2e is the harness's
// single-node graph-replay dispatch — the floor. Final: memset node.

extern "C" void kernel_launch(void* const* d_in, const int* in_sizes, int n_in,
                              void* d_out, int out_size) {
    (void)d_in; (void)in_sizes; (void)n_in;
    cudaMemsetAsync(d_out, 0, (size_t)out_size * sizeof(float), 0);
}